// round 4
// baseline (speedup 1.0000x reference)
#include <cuda_runtime.h>

#define NEGV (-1e9f)

#define B_   32
#define N_   256
#define CIN  1024
#define CH   2048
#define ROWS (B_ * N_)          /* 8192 */

/* ------------- scratch (device globals: the allowed alloc-free path) ---- */
__device__ float g_ax [ROWS * CH];
__device__ float g_ux [ROWS * CH];
__device__ float g_e1 [ROWS * CH];
__device__ float g_e2 [ROWS * CH];
__device__ float g_tb [ROWS * CH];
__device__ float g_m1 [ROWS * CH];
__device__ float g_m2 [ROWS * CH];
__device__ float g_cat[ROWS * 2 * CH];
__device__ float g_sb [B_ * N_ * N_];
__device__ float g_col[2 * ROWS];

/* ------------- packed fp32x2 helpers (Blackwell FFMA2) ------------------ */
__device__ __forceinline__ unsigned long long pk2(float x, float y) {
    unsigned long long r;
    asm("mov.b64 %0, {%1,%2};" : "=l"(r) : "f"(x), "f"(y));
    return r;
}
__device__ __forceinline__ void upk2(unsigned long long v, float& x, float& y) {
    asm("mov.b64 {%0,%1}, %2;" : "=f"(x), "=f"(y) : "l"(v));
}
__device__ __forceinline__ void ffma2(unsigned long long& d, unsigned long long a,
                                      unsigned long long b) {
    asm("fma.rn.f32x2 %0, %1, %2, %0;" : "+l"(d) : "l"(a), "l"(b));
}
__device__ __forceinline__ void addf2(unsigned long long& d, unsigned long long a) {
    asm("add.rn.f32x2 %0, %0, %1;" : "+l"(d) : "l"(a));
}

/* ------------- generic SGEMM: C = op(A) * op(B) (+bias)(relu)(*rowscale)(+addend)
 * A: (M x K) row-major, or if TRA: A[k*lda + m]
 * B: (K x N) row-major, or if TRB: B[n*ldb + k]
 * 128x128x16 tile, 256 threads, 8x8 micro-tile, f32x2 accumulators.
 * Per-K-tile partial accumulation (tacc) shortens the serial fp32 add chain
 * from K to K/16 + 16 -> ~10x lower rounding error (tau=0.05 amplifies it).
 * Software pipeline: double-buffered smem + register staging; LDGs for tile
 * t+1 issue before the 16-kk compute of tile t; ONE barrier per tile. */
template <bool TRA, bool TRB, bool RELU>
__global__ __launch_bounds__(256) void gemm_k(
    int M, int N, int K,
    const float* __restrict__ A, int lda, long long sA,
    const float* __restrict__ Bm, int ldb, long long sB,
    float* __restrict__ C, int ldc, long long sC,
    const float* __restrict__ bias,
    const float* __restrict__ rowscale,
    const float* __restrict__ addend, int ldadd, long long sAdd)
{
    __shared__ float As[2][16][132];
    __shared__ float Bs[2][16][132];
    const int bz = blockIdx.z;
    A  += (long long)bz * sA;
    Bm += (long long)bz * sB;
    C  += (long long)bz * sC;
    const int m0 = blockIdx.x * 128, n0 = blockIdx.y * 128;
    const int tid = threadIdx.x;
    const int tx = tid & 15, ty = tid >> 4;

    /* ---- per-thread global load pointers (advance per K-tile) ---- */
    const float* apt;  long long aStep;
    const float* bpt;  long long bStep;
    if (!TRA) { apt = A  + (long long)(m0 + (tid >> 1)) * lda + ((tid & 1) << 3); aStep = 16; }
    else      { apt = A  + (long long)(tid >> 4) * lda + m0 + ((tid & 15) << 3);  aStep = 16LL * lda; }
    if (!TRB) { bpt = Bm + (long long)(tid >> 4) * ldb + n0 + ((tid & 15) << 3);  bStep = 16LL * ldb; }
    else      { bpt = Bm + (long long)(n0 + (tid >> 1)) * ldb + ((tid & 1) << 3); bStep = 16; }

    float rA[8], rB[8];
    /* ---- stage tile 0 ---- */
    {
        float4 t0 = *(const float4*)apt, t1 = *(const float4*)(apt + 4);
        rA[0]=t0.x; rA[1]=t0.y; rA[2]=t0.z; rA[3]=t0.w;
        rA[4]=t1.x; rA[5]=t1.y; rA[6]=t1.z; rA[7]=t1.w;
        float4 u0 = *(const float4*)bpt, u1 = *(const float4*)(bpt + 4);
        rB[0]=u0.x; rB[1]=u0.y; rB[2]=u0.z; rB[3]=u0.w;
        rB[4]=u1.x; rB[5]=u1.y; rB[6]=u1.z; rB[7]=u1.w;
        apt += aStep; bpt += bStep;
    }

    unsigned long long acc[8][4];
#pragma unroll
    for (int i = 0; i < 8; i++)
#pragma unroll
        for (int j = 0; j < 4; j++) acc[i][j] = 0ull;

    int p = 0;
    /* store staged regs into smem buffer q */
    auto store_tile = [&](int q) {
        if (!TRA) {
            int m = tid >> 1, kq = (tid & 1) << 3;
#pragma unroll
            for (int j = 0; j < 8; j++) As[q][kq + j][m] = rA[j];
        } else {
            int kk = tid >> 4, mq = (tid & 15) << 3;
            *(float4*)&As[q][kk][mq]     = make_float4(rA[0], rA[1], rA[2], rA[3]);
            *(float4*)&As[q][kk][mq + 4] = make_float4(rA[4], rA[5], rA[6], rA[7]);
        }
        if (!TRB) {
            int kk = tid >> 4, nq = (tid & 15) << 3;
            *(float4*)&Bs[q][kk][nq]     = make_float4(rB[0], rB[1], rB[2], rB[3]);
            *(float4*)&Bs[q][kk][nq + 4] = make_float4(rB[4], rB[5], rB[6], rB[7]);
        } else {
            int n = tid >> 1, kq = (tid & 1) << 3;
#pragma unroll
            for (int j = 0; j < 8; j++) Bs[q][kq + j][n] = rB[j];
        }
    };

    store_tile(0);
    __syncthreads();

    const int ntiles = K >> 4;
    for (int t = 0; t < ntiles; ++t) {
        const bool more = (t + 1) < ntiles;
        if (more) {   /* issue LDGs for tile t+1 — consumed ~2048 cyc later */
            float4 t0 = *(const float4*)apt, t1 = *(const float4*)(apt + 4);
            rA[0]=t0.x; rA[1]=t0.y; rA[2]=t0.z; rA[3]=t0.w;
            rA[4]=t1.x; rA[5]=t1.y; rA[6]=t1.z; rA[7]=t1.w;
            float4 u0 = *(const float4*)bpt, u1 = *(const float4*)(bpt + 4);
            rB[0]=u0.x; rB[1]=u0.y; rB[2]=u0.z; rB[3]=u0.w;
            rB[4]=u1.x; rB[5]=u1.y; rB[6]=u1.z; rB[7]=u1.w;
            apt += aStep; bpt += bStep;
        }

        unsigned long long tacc[8][4];
#pragma unroll
        for (int i = 0; i < 8; i++)
#pragma unroll
            for (int j = 0; j < 4; j++) tacc[i][j] = 0ull;

#pragma unroll
        for (int kk = 0; kk < 16; kk++) {
            float a[8];
            *(float4*)&a[0] = *(const float4*)&As[p][kk][ty << 3];
            *(float4*)&a[4] = *(const float4*)&As[p][kk][(ty << 3) + 4];
            float4 b0 = *(const float4*)&Bs[p][kk][tx << 3];
            float4 b1 = *(const float4*)&Bs[p][kk][(tx << 3) + 4];
            unsigned long long bp4[4] = { pk2(b0.x, b0.y), pk2(b0.z, b0.w),
                                          pk2(b1.x, b1.y), pk2(b1.z, b1.w) };
#pragma unroll
            for (int i = 0; i < 8; i++) {
                unsigned long long ai = pk2(a[i], a[i]);
                ffma2(tacc[i][0], ai, bp4[0]);
                ffma2(tacc[i][1], ai, bp4[1]);
                ffma2(tacc[i][2], ai, bp4[2]);
                ffma2(tacc[i][3], ai, bp4[3]);
            }
        }
#pragma unroll
        for (int i = 0; i < 8; i++)
#pragma unroll
            for (int j = 0; j < 4; j++) addf2(acc[i][j], tacc[i][j]);

        if (more) store_tile(p ^ 1);
        __syncthreads();
        p ^= 1;
    }

#pragma unroll
    for (int i = 0; i < 8; i++) {
        const int row  = m0 + (ty << 3) + i;
        const int colb = n0 + (tx << 3);
        float out[8];
#pragma unroll
        for (int j = 0; j < 4; j++) upk2(acc[i][j], out[2 * j], out[2 * j + 1]);
        if (bias) {
#pragma unroll
            for (int j = 0; j < 8; j++) out[j] += bias[colb + j];
        }
        if (RELU) {
#pragma unroll
            for (int j = 0; j < 8; j++) out[j] = fmaxf(out[j], 0.f);
        }
        if (rowscale) {
            float rs = rowscale[row];
#pragma unroll
            for (int j = 0; j < 8; j++) out[j] *= rs;
        }
        if (addend) {
            const float* adp = addend + (long long)bz * sAdd + (long long)row * ldadd + colb;
#pragma unroll
            for (int j = 0; j < 8; j++) out[j] += adp[j];
        }
        float* cp = C + (long long)row * ldc + colb;
        *(float4*)cp       = make_float4(out[0], out[1], out[2], out[3]);
        *(float4*)(cp + 4) = make_float4(out[4], out[5], out[6], out[7]);
    }
}

/* ------------- inverse column-L1 norms of A: inv[b*256+m] = 1/max(sum_n|A|,1e-12) */
__global__ void colnorm_kernel(const float* __restrict__ A, float* __restrict__ inv)
{
    int g = blockIdx.x * blockDim.x + threadIdx.x;   /* 0..8191 */
    int b = g >> 8, m = g & 255;
    const float* base = A + (long long)b * 65536 + m;
    float s = 0.f;
#pragma unroll 8
    for (int n = 0; n < 256; n++) s += fabsf(base[n * 256]);
    inv[g] = 1.f / fmaxf(s, 1e-12f);
}

/* ------------- copy (8192 x 2048) into left half of (8192 x 4096) ------- */
__global__ void copycat_kernel(const float* __restrict__ src, float* __restrict__ dst)
{
    long long i = (long long)blockIdx.x * blockDim.x + threadIdx.x;  /* float4 idx */
    long long row = i >> 9;          /* / 512 */
    long long c4  = i & 511;
    ((float4*)dst)[(row << 10) + c4] = ((const float4*)src)[i];
}

/* ------------- masked Sinkhorn, one CTA per batch, data in global/L2 ---- */
__global__ __launch_bounds__(1024) void sinkhorn_kernel(
    float* __restrict__ buf, float* __restrict__ out,
    const int* __restrict__ n1, const int* __restrict__ iters_ptr)
{
    __shared__ float red[4 * 256];
    __shared__ float lsebuf[256];
    const int b = blockIdx.x;
    float* Mb = buf + (long long)b * 65536;
    const int nv = n1[b];
    const int iters = *iters_ptr;
    const int tid = threadIdx.x;
    const int warp = tid >> 5, lane = tid & 31;

    /* init: log_s = mask ? s/tau : NEG   (tau = 0.05, cols all valid) */
    for (int idx = tid; idx < 65536; idx += 1024) {
        int r = idx >> 8;
        float v = Mb[idx];
        Mb[idx] = (r < nv) ? v / 0.05f : NEGV;
    }
    __syncthreads();

    for (int it = 0; it < iters; ++it) {
        if ((it & 1) == 0) {
            /* row-normalize: lse over columns */
            for (int r = warp; r < 256; r += 32) {
                float* rp = Mb + (r << 8);
                float v[8];
#pragma unroll
                for (int j = 0; j < 8; j++) v[j] = rp[lane + (j << 5)];
                float mx = v[0];
#pragma unroll
                for (int j = 1; j < 8; j++) mx = fmaxf(mx, v[j]);
#pragma unroll
                for (int o = 16; o > 0; o >>= 1)
                    mx = fmaxf(mx, __shfl_xor_sync(0xffffffffu, mx, o));
                float sm = 0.f;
#pragma unroll
                for (int j = 0; j < 8; j++) sm += expf(v[j] - mx);
#pragma unroll
                for (int o = 16; o > 0; o >>= 1)
                    sm += __shfl_xor_sync(0xffffffffu, sm, o);
                float lse = mx + logf(sm);
                bool ok = r < nv;
#pragma unroll
                for (int j = 0; j < 8; j++)
                    rp[lane + (j << 5)] = ok ? (v[j] - lse) : NEGV;
            }
            __syncthreads();
        } else {
            /* col-normalize: lse over rows */
            const int c = tid & 255, g = tid >> 8;
            float pm = NEGV;
            for (int r = g; r < 256; r += 4) pm = fmaxf(pm, Mb[(r << 8) + c]);
            red[(g << 8) + c] = pm;
            __syncthreads();
            if (tid < 256) {
                float cm = fmaxf(fmaxf(red[tid], red[256 + tid]),
                                 fmaxf(red[512 + tid], red[768 + tid]));
                lsebuf[tid] = cm;
            }
            __syncthreads();
            float cm = lsebuf[c];
            float ps = 0.f;
            for (int r = g; r < 256; r += 4) ps += expf(Mb[(r << 8) + c] - cm);
            red[(g << 8) + c] = ps;
            __syncthreads();
            if (tid < 256) {
                float s4 = red[tid] + red[256 + tid] + red[512 + tid] + red[768 + tid];
                lsebuf[tid] = lsebuf[tid] + logf(s4);
            }
            __syncthreads();
            for (int idx = tid; idx < 65536; idx += 1024) {
                int r = idx >> 8, cc = idx & 255;
                Mb[idx] = (r < nv) ? (Mb[idx] - lsebuf[cc]) : NEGV;
            }
            __syncthreads();
        }
    }
    float* ob = out + (long long)b * 65536;
    for (int idx = tid; idx < 65536; idx += 1024)
        ob[idx] = expf(Mb[idx]);     /* exp(NEG) underflows to exactly 0 */
}

/* ------------- orchestration -------------------------------------------- */
extern "C" void kernel_launch(void* const* d_in, const int* in_sizes, int n_in,
                              void* d_out, int out_size)
{
    (void)in_sizes; (void)n_in; (void)out_size;
    const float* feat1 = (const float*)d_in[0];
    const float* feat2 = (const float*)d_in[1];
    const float* A1p   = (const float*)d_in[2];
    const float* A2p   = (const float*)d_in[3];
    const int*   n1p   = (const int*)d_in[4];
    /* d_in[5]=n2 (all 256), d_in[6]=cross_iter_num: unused */
    const int*   skp   = (const int*)d_in[7];
    const float* W0a = (const float*)d_in[8],  *b0a = (const float*)d_in[9];
    const float* W0u = (const float*)d_in[10], *b0u = (const float*)d_in[11];
    const float* W1a = (const float*)d_in[12], *b1a = (const float*)d_in[13];
    const float* W1u = (const float*)d_in[14], *b1u = (const float*)d_in[15];
    const float* Wc  = (const float*)d_in[16], *bc  = (const float*)d_in[17];
    const float* Aaff0 = (const float*)d_in[18];
    const float* Aaff1 = (const float*)d_in[19];
    float* outp = (float*)d_out;

    float *ax, *ux, *e1, *e2, *tb, *m1, *m2, *cat, *sb, *col;
    cudaGetSymbolAddress((void**)&ax,  g_ax);
    cudaGetSymbolAddress((void**)&ux,  g_ux);
    cudaGetSymbolAddress((void**)&e1,  g_e1);
    cudaGetSymbolAddress((void**)&e2,  g_e2);
    cudaGetSymbolAddress((void**)&tb,  g_tb);
    cudaGetSymbolAddress((void**)&m1,  g_m1);
    cudaGetSymbolAddress((void**)&m2,  g_m2);
    cudaGetSymbolAddress((void**)&cat, g_cat);
    cudaGetSymbolAddress((void**)&sb,  g_sb);
    cudaGetSymbolAddress((void**)&col, g_col);

    const dim3 blk(256);
    const long long SE = 256LL * 2048;     /* per-batch stride of emb rows */
    const long long SS = 65536LL;          /* per-batch stride of s        */
    const long long SCAT = 256LL * 4096;

    /* column L1 norms (shared by both gconv layers) */
    colnorm_kernel<<<32, 256>>>(A1p, col);
    colnorm_kernel<<<32, 256>>>(A2p, col + ROWS);

    /* ---- gconv layer 0, graph 1 ---- */
    gemm_k<false,false,true ><<<dim3(64,16,1), blk>>>(8192,2048,1024, feat1,1024,0, W0a,2048,0, ax,2048,0, b0a, col,        nullptr,0,0);
    gemm_k<false,false,true ><<<dim3(64,16,1), blk>>>(8192,2048,1024, feat1,1024,0, W0u,2048,0, ux,2048,0, b0u, nullptr,    nullptr,0,0);
    gemm_k<false,false,false><<<dim3(2,16,32), blk>>>(256,2048,256, A1p,256,SS, ax,2048,SE, e1,2048,SE, nullptr,nullptr, ux,2048,SE);
    /* ---- gconv layer 0, graph 2 ---- */
    gemm_k<false,false,true ><<<dim3(64,16,1), blk>>>(8192,2048,1024, feat2,1024,0, W0a,2048,0, ax,2048,0, b0a, col+ROWS,   nullptr,0,0);
    gemm_k<false,false,true ><<<dim3(64,16,1), blk>>>(8192,2048,1024, feat2,1024,0, W0u,2048,0, ux,2048,0, b0u, nullptr,    nullptr,0,0);
    gemm_k<false,false,false><<<dim3(2,16,32), blk>>>(256,2048,256, A2p,256,SS, ax,2048,SE, e2,2048,SE, nullptr,nullptr, ux,2048,SE);

    /* ---- affinity 0: s = (e1 @ Aaff0) @ e2^T, then sinkhorn ---- */
    gemm_k<false,false,false><<<dim3(64,16,1), blk>>>(8192,2048,2048, e1,2048,0, Aaff0,2048,0, tb,2048,0, nullptr,nullptr,nullptr,0,0);
    gemm_k<false,true ,false><<<dim3(2,2,32),  blk>>>(256,256,2048, tb,2048,SE, e2,2048,SE, sb,256,SS, nullptr,nullptr,nullptr,0,0);
    sinkhorn_kernel<<<32, 1024>>>(sb, sb, n1p, skp);

    /* ---- cross update ---- */
    copycat_kernel<<<16384, 256>>>(e1, cat);
    gemm_k<false,false,false><<<dim3(2,16,32), blk>>>(256,2048,256, sb,256,SS, e2,2048,SE, cat+2048,4096,SCAT, nullptr,nullptr,nullptr,0,0);
    gemm_k<false,false,false><<<dim3(64,16,1), blk>>>(8192,2048,4096, cat,4096,0, Wc,2048,0, m1,2048,0, bc, nullptr, nullptr,0,0);
    copycat_kernel<<<16384, 256>>>(e2, cat);
    gemm_k<true ,false,false><<<dim3(2,16,32), blk>>>(256,2048,256, sb,256,SS, e1,2048,SE, cat+2048,4096,SCAT, nullptr,nullptr,nullptr,0,0);
    gemm_k<false,false,false><<<dim3(64,16,1), blk>>>(8192,2048,4096, cat,4096,0, Wc,2048,0, m2,2048,0, bc, nullptr, nullptr,0,0);

    /* ---- gconv layer 1, graph 1 ---- */
    gemm_k<false,false,true ><<<dim3(64,16,1), blk>>>(8192,2048,2048, m1,2048,0, W1a,2048,0, ax,2048,0, b1a, col,      nullptr,0,0);
    gemm_k<false,false,true ><<<dim3(64,16,1), blk>>>(8192,2048,2048, m1,2048,0, W1u,2048,0, ux,2048,0, b1u, nullptr,  nullptr,0,0);
    gemm_k<false,false,false><<<dim3(2,16,32), blk>>>(256,2048,256, A1p,256,SS, ax,2048,SE, e1,2048,SE, nullptr,nullptr, ux,2048,SE);
    /* ---- gconv layer 1, graph 2 ---- */
    gemm_k<false,false,true ><<<dim3(64,16,1), blk>>>(8192,2048,2048, m2,2048,0, W1a,2048,0, ax,2048,0, b1a, col+ROWS, nullptr,0,0);
    gemm_k<false,false,true ><<<dim3(64,16,1), blk>>>(8192,2048,2048, m2,2048,0, W1u,2048,0, ux,2048,0, b1u, nullptr,  nullptr,0,0);
    gemm_k<false,false,false><<<dim3(2,16,32), blk>>>(256,2048,256, A2p,256,SS, ax,2048,SE, e2,2048,SE, nullptr,nullptr, ux,2048,SE);

    /* ---- affinity 1 + final sinkhorn -> output ---- */
    gemm_k<false,false,false><<<dim3(64,16,1), blk>>>(8192,2048,2048, e1,2048,0, Aaff1,2048,0, tb,2048,0, nullptr,nullptr,nullptr,0,0);
    gemm_k<false,true ,false><<<dim3(2,2,32),  blk>>>(256,256,2048, tb,2048,SE, e2,2048,SE, sb,256,SS, nullptr,nullptr,nullptr,0,0);
    sinkhorn_kernel<<<32, 1024>>>(sb, outp, n1p, skp);
}

// round 5
// speedup vs baseline: 1.4268x; 1.4268x over previous
#include <cuda_runtime.h>

#define NEGV (-1e9f)

#define B_   32
#define N_   256
#define CIN  1024
#define CH   2048
#define ROWS (B_ * N_)          /* 8192 */

/* ------------- scratch (device globals: the allowed alloc-free path) ---- */
__device__ float g_ax [ROWS * CH];
__device__ float g_ux [ROWS * CH];
__device__ float g_e1 [ROWS * CH];
__device__ float g_e2 [ROWS * CH];
__device__ float g_tb [ROWS * CH];
__device__ float g_m1 [ROWS * CH];
__device__ float g_m2 [ROWS * CH];
__device__ float g_cat[ROWS * 2 * CH];
__device__ float g_sb [B_ * N_ * N_];
__device__ float g_col[2 * ROWS];

/* ------------- packed fp32x2 helpers (Blackwell FFMA2) ------------------ */
__device__ __forceinline__ unsigned long long pk2(float x, float y) {
    unsigned long long r;
    asm("mov.b64 %0, {%1,%2};" : "=l"(r) : "f"(x), "f"(y));
    return r;
}
__device__ __forceinline__ void upk2(unsigned long long v, float& x, float& y) {
    asm("mov.b64 {%0,%1}, %2;" : "=f"(x), "=f"(y) : "l"(v));
}
__device__ __forceinline__ void ffma2(unsigned long long& d, unsigned long long a,
                                      unsigned long long b) {
    asm("fma.rn.f32x2 %0, %1, %2, %0;" : "+l"(d) : "l"(a), "l"(b));
}
__device__ __forceinline__ void addf2(unsigned long long& d, unsigned long long a) {
    asm("add.rn.f32x2 %0, %0, %1;" : "+l"(d) : "l"(a));
}

/* ------------- generic SGEMM: C = op(A) * op(B) (+bias)(relu)(*rowscale)(+addend)
 * A: (M x K) row-major, or if TRA: A[k*lda + m]
 * B: (K x N) row-major, or if TRB: B[n*ldb + k]
 * 128x128x16 tile, 512 threads, 8x4 micro-tile, f32x2 accumulators.
 * 512 threads -> 16 warps -> 4 warps/SMSP for latency hiding (R2 had 2).
 * Per-K-tile partial accumulation (tacc) keeps the serial fp32 add chain at
 * K/16 + 16 -> rounding stays ~5.9e-4 (tau=0.05 amplifies GEMM error). */
template <bool TRA, bool TRB, bool RELU>
__global__ __launch_bounds__(512) void gemm_k(
    int M, int N, int K,
    const float* __restrict__ A, int lda, long long sA,
    const float* __restrict__ Bm, int ldb, long long sB,
    float* __restrict__ C, int ldc, long long sC,
    const float* __restrict__ bias,
    const float* __restrict__ rowscale,
    const float* __restrict__ addend, int ldadd, long long sAdd)
{
    __shared__ float As[16][132];
    __shared__ float Bs[16][132];
    const int bz = blockIdx.z;
    A  += (long long)bz * sA;
    Bm += (long long)bz * sB;
    C  += (long long)bz * sC;
    const int m0 = blockIdx.x * 128, n0 = blockIdx.y * 128;
    const int tid = threadIdx.x;
    const int tx = tid & 31, ty = tid >> 5;   /* micro-tile: rows ty*8.., cols tx*4.. */

    unsigned long long acc[8][2];
#pragma unroll
    for (int i = 0; i < 8; i++) { acc[i][0] = 0ull; acc[i][1] = 0ull; }

    for (int k0 = 0; k0 < K; k0 += 16) {
        /* ---- load tile: each thread moves ONE float4 of A and ONE of B ---- */
        if (!TRA) {
            int m = tid >> 2, kq = (tid & 3) << 2;
            const float* ap = A + (long long)(m0 + m) * lda + k0 + kq;
            float4 a0 = *(const float4*)ap;
            As[kq + 0][m] = a0.x; As[kq + 1][m] = a0.y;
            As[kq + 2][m] = a0.z; As[kq + 3][m] = a0.w;
        } else {
            int kk = tid >> 5, mq = (tid & 31) << 2;
            *(float4*)&As[kk][mq] =
                *(const float4*)(A + (long long)(k0 + kk) * lda + m0 + mq);
        }
        if (!TRB) {
            int kk = tid >> 5, nq = (tid & 31) << 2;
            *(float4*)&Bs[kk][nq] =
                *(const float4*)(Bm + (long long)(k0 + kk) * ldb + n0 + nq);
        } else {
            int n = tid >> 2, kq = (tid & 3) << 2;
            const float* bp = Bm + (long long)(n0 + n) * ldb + k0 + kq;
            float4 b0 = *(const float4*)bp;
            Bs[kq + 0][n] = b0.x; Bs[kq + 1][n] = b0.y;
            Bs[kq + 2][n] = b0.z; Bs[kq + 3][n] = b0.w;
        }
        __syncthreads();

        unsigned long long tacc[8][2];
#pragma unroll
        for (int i = 0; i < 8; i++) { tacc[i][0] = 0ull; tacc[i][1] = 0ull; }

#pragma unroll
        for (int kk = 0; kk < 16; kk++) {
            float a[8];
            *(float4*)&a[0] = *(const float4*)&As[kk][ty << 3];
            *(float4*)&a[4] = *(const float4*)&As[kk][(ty << 3) + 4];
            float4 b = *(const float4*)&Bs[kk][tx << 2];
            unsigned long long bp2[2] = { pk2(b.x, b.y), pk2(b.z, b.w) };
#pragma unroll
            for (int i = 0; i < 8; i++) {
                unsigned long long ai = pk2(a[i], a[i]);
                ffma2(tacc[i][0], ai, bp2[0]);
                ffma2(tacc[i][1], ai, bp2[1]);
            }
        }
#pragma unroll
        for (int i = 0; i < 8; i++) {
            addf2(acc[i][0], tacc[i][0]);
            addf2(acc[i][1], tacc[i][1]);
        }
        __syncthreads();
    }

#pragma unroll
    for (int i = 0; i < 8; i++) {
        const int row  = m0 + (ty << 3) + i;
        const int colb = n0 + (tx << 2);
        float out[4];
        upk2(acc[i][0], out[0], out[1]);
        upk2(acc[i][1], out[2], out[3]);
        if (bias) {
#pragma unroll
            for (int j = 0; j < 4; j++) out[j] += bias[colb + j];
        }
        if (RELU) {
#pragma unroll
            for (int j = 0; j < 4; j++) out[j] = fmaxf(out[j], 0.f);
        }
        if (rowscale) {
            float rs = rowscale[row];
#pragma unroll
            for (int j = 0; j < 4; j++) out[j] *= rs;
        }
        if (addend) {
            const float* adp = addend + (long long)bz * sAdd + (long long)row * ldadd + colb;
#pragma unroll
            for (int j = 0; j < 4; j++) out[j] += adp[j];
        }
        *(float4*)(C + (long long)row * ldc + colb) =
            make_float4(out[0], out[1], out[2], out[3]);
    }
}

/* ------------- inverse column-L1 norms of A: inv[b*256+m] = 1/max(sum_n|A|,1e-12) */
__global__ void colnorm_kernel(const float* __restrict__ A, float* __restrict__ inv)
{
    int g = blockIdx.x * blockDim.x + threadIdx.x;   /* 0..8191 */
    int b = g >> 8, m = g & 255;
    const float* base = A + (long long)b * 65536 + m;
    float s = 0.f;
#pragma unroll 8
    for (int n = 0; n < 256; n++) s += fabsf(base[n * 256]);
    inv[g] = 1.f / fmaxf(s, 1e-12f);
}

/* ------------- copy (8192 x 2048) into left half of (8192 x 4096) ------- */
__global__ void copycat_kernel(const float* __restrict__ src, float* __restrict__ dst)
{
    long long i = (long long)blockIdx.x * blockDim.x + threadIdx.x;  /* float4 idx */
    long long row = i >> 9;          /* / 512 */
    long long c4  = i & 511;
    ((float4*)dst)[(row << 10) + c4] = ((const float4*)src)[i];
}

/* ------------- masked Sinkhorn, one CTA per batch, data in global/L2 ---- */
__global__ __launch_bounds__(1024) void sinkhorn_kernel(
    float* __restrict__ buf, float* __restrict__ out,
    const int* __restrict__ n1, const int* __restrict__ iters_ptr)
{
    __shared__ float red[4 * 256];
    __shared__ float lsebuf[256];
    const int b = blockIdx.x;
    float* Mb = buf + (long long)b * 65536;
    const int nv = n1[b];
    const int iters = *iters_ptr;
    const int tid = threadIdx.x;
    const int warp = tid >> 5, lane = tid & 31;

    /* init: log_s = mask ? s/tau : NEG   (tau = 0.05, cols all valid) */
    for (int idx = tid; idx < 65536; idx += 1024) {
        int r = idx >> 8;
        float v = Mb[idx];
        Mb[idx] = (r < nv) ? v / 0.05f : NEGV;
    }
    __syncthreads();

    for (int it = 0; it < iters; ++it) {
        if ((it & 1) == 0) {
            /* row-normalize: lse over columns */
            for (int r = warp; r < 256; r += 32) {
                float* rp = Mb + (r << 8);
                float v[8];
#pragma unroll
                for (int j = 0; j < 8; j++) v[j] = rp[lane + (j << 5)];
                float mx = v[0];
#pragma unroll
                for (int j = 1; j < 8; j++) mx = fmaxf(mx, v[j]);
#pragma unroll
                for (int o = 16; o > 0; o >>= 1)
                    mx = fmaxf(mx, __shfl_xor_sync(0xffffffffu, mx, o));
                float sm = 0.f;
#pragma unroll
                for (int j = 0; j < 8; j++) sm += expf(v[j] - mx);
#pragma unroll
                for (int o = 16; o > 0; o >>= 1)
                    sm += __shfl_xor_sync(0xffffffffu, sm, o);
                float lse = mx + logf(sm);
                bool ok = r < nv;
#pragma unroll
                for (int j = 0; j < 8; j++)
                    rp[lane + (j << 5)] = ok ? (v[j] - lse) : NEGV;
            }
            __syncthreads();
        } else {
            /* col-normalize: lse over rows */
            const int c = tid & 255, g = tid >> 8;
            float pm = NEGV;
            for (int r = g; r < 256; r += 4) pm = fmaxf(pm, Mb[(r << 8) + c]);
            red[(g << 8) + c] = pm;
            __syncthreads();
            if (tid < 256) {
                float cm = fmaxf(fmaxf(red[tid], red[256 + tid]),
                                 fmaxf(red[512 + tid], red[768 + tid]));
                lsebuf[tid] = cm;
            }
            __syncthreads();
            float cm = lsebuf[c];
            float ps = 0.f;
            for (int r = g; r < 256; r += 4) ps += expf(Mb[(r << 8) + c] - cm);
            red[(g << 8) + c] = ps;
            __syncthreads();
            if (tid < 256) {
                float s4 = red[tid] + red[256 + tid] + red[512 + tid] + red[768 + tid];
                lsebuf[tid] = lsebuf[tid] + logf(s4);
            }
            __syncthreads();
            for (int idx = tid; idx < 65536; idx += 1024) {
                int r = idx >> 8, cc = idx & 255;
                Mb[idx] = (r < nv) ? (Mb[idx] - lsebuf[cc]) : NEGV;
            }
            __syncthreads();
        }
    }
    float* ob = out + (long long)b * 65536;
    for (int idx = tid; idx < 65536; idx += 1024)
        ob[idx] = expf(Mb[idx]);     /* exp(NEG) underflows to exactly 0 */
}

/* ------------- orchestration -------------------------------------------- */
extern "C" void kernel_launch(void* const* d_in, const int* in_sizes, int n_in,
                              void* d_out, int out_size)
{
    (void)in_sizes; (void)n_in; (void)out_size;
    const float* feat1 = (const float*)d_in[0];
    const float* feat2 = (const float*)d_in[1];
    const float* A1p   = (const float*)d_in[2];
    const float* A2p   = (const float*)d_in[3];
    const int*   n1p   = (const int*)d_in[4];
    /* d_in[5]=n2 (all 256), d_in[6]=cross_iter_num: unused */
    const int*   skp   = (const int*)d_in[7];
    const float* W0a = (const float*)d_in[8],  *b0a = (const float*)d_in[9];
    const float* W0u = (const float*)d_in[10], *b0u = (const float*)d_in[11];
    const float* W1a = (const float*)d_in[12], *b1a = (const float*)d_in[13];
    const float* W1u = (const float*)d_in[14], *b1u = (const float*)d_in[15];
    const float* Wc  = (const float*)d_in[16], *bc  = (const float*)d_in[17];
    const float* Aaff0 = (const float*)d_in[18];
    const float* Aaff1 = (const float*)d_in[19];
    float* outp = (float*)d_out;

    float *ax, *ux, *e1, *e2, *tb, *m1, *m2, *cat, *sb, *col;
    cudaGetSymbolAddress((void**)&ax,  g_ax);
    cudaGetSymbolAddress((void**)&ux,  g_ux);
    cudaGetSymbolAddress((void**)&e1,  g_e1);
    cudaGetSymbolAddress((void**)&e2,  g_e2);
    cudaGetSymbolAddress((void**)&tb,  g_tb);
    cudaGetSymbolAddress((void**)&m1,  g_m1);
    cudaGetSymbolAddress((void**)&m2,  g_m2);
    cudaGetSymbolAddress((void**)&cat, g_cat);
    cudaGetSymbolAddress((void**)&sb,  g_sb);
    cudaGetSymbolAddress((void**)&col, g_col);

    const dim3 blk(512);
    const long long SE = 256LL * 2048;     /* per-batch stride of emb rows */
    const long long SS = 65536LL;          /* per-batch stride of s        */
    const long long SCAT = 256LL * 4096;

    /* column L1 norms (shared by both gconv layers) */
    colnorm_kernel<<<32, 256>>>(A1p, col);
    colnorm_kernel<<<32, 256>>>(A2p, col + ROWS);

    /* ---- gconv layer 0, graph 1 ---- */
    gemm_k<false,false,true ><<<dim3(64,16,1), blk>>>(8192,2048,1024, feat1,1024,0, W0a,2048,0, ax,2048,0, b0a, col,        nullptr,0,0);
    gemm_k<false,false,true ><<<dim3(64,16,1), blk>>>(8192,2048,1024, feat1,1024,0, W0u,2048,0, ux,2048,0, b0u, nullptr,    nullptr,0,0);
    gemm_k<false,false,false><<<dim3(2,16,32), blk>>>(256,2048,256, A1p,256,SS, ax,2048,SE, e1,2048,SE, nullptr,nullptr, ux,2048,SE);
    /* ---- gconv layer 0, graph 2 ---- */
    gemm_k<false,false,true ><<<dim3(64,16,1), blk>>>(8192,2048,1024, feat2,1024,0, W0a,2048,0, ax,2048,0, b0a, col+ROWS,   nullptr,0,0);
    gemm_k<false,false,true ><<<dim3(64,16,1), blk>>>(8192,2048,1024, feat2,1024,0, W0u,2048,0, ux,2048,0, b0u, nullptr,    nullptr,0,0);
    gemm_k<false,false,false><<<dim3(2,16,32), blk>>>(256,2048,256, A2p,256,SS, ax,2048,SE, e2,2048,SE, nullptr,nullptr, ux,2048,SE);

    /* ---- affinity 0: s = (e1 @ Aaff0) @ e2^T, then sinkhorn ---- */
    gemm_k<false,false,false><<<dim3(64,16,1), blk>>>(8192,2048,2048, e1,2048,0, Aaff0,2048,0, tb,2048,0, nullptr,nullptr,nullptr,0,0);
    gemm_k<false,true ,false><<<dim3(2,2,32),  blk>>>(256,256,2048, tb,2048,SE, e2,2048,SE, sb,256,SS, nullptr,nullptr,nullptr,0,0);
    sinkhorn_kernel<<<32, 1024>>>(sb, sb, n1p, skp);

    /* ---- cross update ---- */
    copycat_kernel<<<16384, 256>>>(e1, cat);
    gemm_k<false,false,false><<<dim3(2,16,32), blk>>>(256,2048,256, sb,256,SS, e2,2048,SE, cat+2048,4096,SCAT, nullptr,nullptr,nullptr,0,0);
    gemm_k<false,false,false><<<dim3(64,16,1), blk>>>(8192,2048,4096, cat,4096,0, Wc,2048,0, m1,2048,0, bc, nullptr, nullptr,0,0);
    copycat_kernel<<<16384, 256>>>(e2, cat);
    gemm_k<true ,false,false><<<dim3(2,16,32), blk>>>(256,2048,256, sb,256,SS, e1,2048,SE, cat+2048,4096,SCAT, nullptr,nullptr,nullptr,0,0);
    gemm_k<false,false,false><<<dim3(64,16,1), blk>>>(8192,2048,4096, cat,4096,0, Wc,2048,0, m2,2048,0, bc, nullptr, nullptr,0,0);

    /* ---- gconv layer 1, graph 1 ---- */
    gemm_k<false,false,true ><<<dim3(64,16,1), blk>>>(8192,2048,2048, m1,2048,0, W1a,2048,0, ax,2048,0, b1a, col,      nullptr,0,0);
    gemm_k<false,false,true ><<<dim3(64,16,1), blk>>>(8192,2048,2048, m1,2048,0, W1u,2048,0, ux,2048,0, b1u, nullptr,  nullptr,0,0);
    gemm_k<false,false,false><<<dim3(2,16,32), blk>>>(256,2048,256, A1p,256,SS, ax,2048,SE, e1,2048,SE, nullptr,nullptr, ux,2048,SE);
    /* ---- gconv layer 1, graph 2 ---- */
    gemm_k<false,false,true ><<<dim3(64,16,1), blk>>>(8192,2048,2048, m2,2048,0, W1a,2048,0, ax,2048,0, b1a, col+ROWS, nullptr,0,0);
    gemm_k<false,false,true ><<<dim3(64,16,1), blk>>>(8192,2048,2048, m2,2048,0, W1u,2048,0, ux,2048,0, b1u, nullptr,  nullptr,0,0);
    gemm_k<false,false,false><<<dim3(2,16,32), blk>>>(256,2048,256, A2p,256,SS, ax,2048,SE, e2,2048,SE, nullptr,nullptr, ux,2048,SE);

    /* ---- affinity 1 + final sinkhorn -> output ---- */
    gemm_k<false,false,false><<<dim3(64,16,1), blk>>>(8192,2048,2048, e1,2048,0, Aaff1,2048,0, tb,2048,0, nullptr,nullptr,nullptr,0,0);
    gemm_k<false,true ,false><<<dim3(2,2,32),  blk>>>(256,256,2048, tb,2048,SE, e2,2048,SE, sb,256,SS, nullptr,nullptr,nullptr,0,0);
    sinkhorn_kernel<<<32, 1024>>>(sb, outp, n1p, skp);
}

// round 6
// speedup vs baseline: 1.6823x; 1.1791x over previous
#include <cuda_runtime.h>

#define NEGV (-1e9f)

#define B_   32
#define N_   256
#define CIN  1024
#define CH   2048
#define ROWS (B_ * N_)          /* 8192 */

#define KT    16
#define STG   3
#define ASZ   (128 * KT)        /* floats per A stage  */
#define BSZ   (KT * 128)        /* floats per B stage  */
#define STAGE (ASZ + BSZ)       /* 4096 floats = 16 KB */
#define SMEMB (STG * STAGE * 4) /* 49152 B dynamic     */

/* ------------- scratch (device globals: the allowed alloc-free path) ---- */
__device__ float g_ax [ROWS * CH];
__device__ float g_ux [ROWS * CH];
__device__ float g_e1 [ROWS * CH];
__device__ float g_e2 [ROWS * CH];
__device__ float g_tb [ROWS * CH];
__device__ float g_m1 [ROWS * CH];
__device__ float g_m2 [ROWS * CH];
__device__ float g_e2t[ROWS * CH];
__device__ float g_cat[ROWS * 2 * CH];
__device__ float g_sb [B_ * N_ * N_];
__device__ float g_sbt[B_ * N_ * N_];
__device__ float g_col[2 * ROWS];

/* ------------- packed fp32x2 helpers (Blackwell FFMA2) ------------------ */
__device__ __forceinline__ unsigned long long pk2(float x, float y) {
    unsigned long long r;
    asm("mov.b64 %0, {%1,%2};" : "=l"(r) : "f"(x), "f"(y));
    return r;
}
__device__ __forceinline__ void upk2(unsigned long long v, float& x, float& y) {
    asm("mov.b64 {%0,%1}, %2;" : "=f"(x), "=f"(y) : "l"(v));
}
__device__ __forceinline__ void ffma2(unsigned long long& d, unsigned long long a,
                                      unsigned long long b) {
    asm("fma.rn.f32x2 %0, %1, %2, %0;" : "+l"(d) : "l"(a), "l"(b));
}
__device__ __forceinline__ void addf2(unsigned long long& d, unsigned long long a) {
    asm("add.rn.f32x2 %0, %0, %1;" : "+l"(d) : "l"(a));
}
__device__ __forceinline__ void cpasync16(unsigned saddr, const float* g) {
    asm volatile("cp.async.ca.shared.global [%0], [%1], 16;" :: "r"(saddr), "l"(g));
}

/* ------------- SGEMM: C = A * B (+bias)(relu)(*rowscale)(+addend)
 * A: (M x K) row-major; B: (K x N) row-major. All dims multiples of tile.
 * 128x128x16 tile, 512 threads, 8x4 micro-tile, f32x2 accumulators.
 * 3-stage cp.async pipeline (prefetch depth 2) -> global latency hidden.
 * A in smem row-major [m][KT] (broadcast scalar reads, crossbar-free);
 * B in smem [kk][128] (conflict-free vector reads).
 * tacc per-K-tile partial accumulation: identical FFMA2/add ordering to the
 * R4 kernel -> rel_err unchanged. */
template <bool RELU>
__global__ __launch_bounds__(512) void gemm_k(
    int M, int N, int K,
    const float* __restrict__ A, int lda, long long sA,
    const float* __restrict__ Bm, int ldb, long long sB,
    float* __restrict__ C, int ldc, long long sC,
    const float* __restrict__ bias,
    const float* __restrict__ rowscale,
    const float* __restrict__ addend, int ldadd, long long sAdd)
{
    extern __shared__ float sm[];
    const int bz = blockIdx.z;
    A  += (long long)bz * sA;
    Bm += (long long)bz * sB;
    C  += (long long)bz * sC;
    const int m0 = blockIdx.x * 128, n0 = blockIdx.y * 128;
    const int tid = threadIdx.x;
    const int tx = tid & 31, ty = tid >> 5;

    /* copy mapping: each thread moves one float4 of A and one of B per tile */
    const int am = tid >> 2,  ac4 = (tid & 3) << 2;   /* A row, col offset   */
    const int bk = tid >> 5,  bc4 = (tid & 31) << 2;  /* B row (k), col off  */
    const float* agp = A  + (long long)(m0 + am) * lda + ac4;
    const float* bgp = Bm + (long long)bk * ldb + n0 + bc4;
    unsigned aso = (unsigned)__cvta_generic_to_shared(sm) + (am * KT + ac4) * 4;
    unsigned bso = (unsigned)__cvta_generic_to_shared(sm) + (ASZ + bk * 128 + bc4) * 4;

    const int ntiles = K >> 4;

#define ISSUE(t, s) do {                                            \
        cpasync16(aso + (s) * (STAGE * 4), agp + (long long)(t) * KT);       \
        cpasync16(bso + (s) * (STAGE * 4), bgp + (long long)(t) * KT * ldb); \
        asm volatile("cp.async.commit_group;");                     \
    } while (0)

    ISSUE(0, 0);
    ISSUE(1, 1);

    unsigned long long acc[8][2];
#pragma unroll
    for (int i = 0; i < 8; i++) { acc[i][0] = 0ull; acc[i][1] = 0ull; }

    int s = 0;
    for (int t = 0; t < ntiles; ++t) {
        if (t + 1 < ntiles) asm volatile("cp.async.wait_group 1;");
        else                asm volatile("cp.async.wait_group 0;");
        __syncthreads();
        if (t + 2 < ntiles) {
            int s2 = s + 2; if (s2 >= STG) s2 -= STG;
            ISSUE(t + 2, s2);
        }
        const float* as = sm + s * STAGE + (ty << 3) * KT;  /* rows ty*8..   */
        const float* bs = sm + s * STAGE + ASZ;

        unsigned long long tacc[8][2];
#pragma unroll
        for (int i = 0; i < 8; i++) { tacc[i][0] = 0ull; tacc[i][1] = 0ull; }

#pragma unroll
        for (int kk = 0; kk < 16; kk++) {
            float a[8];
#pragma unroll
            for (int i = 0; i < 8; i++) a[i] = as[i * KT + kk];   /* broadcast */
            float4 b = *(const float4*)&bs[kk * 128 + (tx << 2)];
            unsigned long long bp2[2] = { pk2(b.x, b.y), pk2(b.z, b.w) };
#pragma unroll
            for (int i = 0; i < 8; i++) {
                unsigned long long ai = pk2(a[i], a[i]);
                ffma2(tacc[i][0], ai, bp2[0]);
                ffma2(tacc[i][1], ai, bp2[1]);
            }
        }
#pragma unroll
        for (int i = 0; i < 8; i++) {
            addf2(acc[i][0], tacc[i][0]);
            addf2(acc[i][1], tacc[i][1]);
        }
        __syncthreads();
        if (++s == STG) s = 0;
    }
#undef ISSUE

#pragma unroll
    for (int i = 0; i < 8; i++) {
        const int row  = m0 + (ty << 3) + i;
        const int colb = n0 + (tx << 2);
        float out[4];
        upk2(acc[i][0], out[0], out[1]);
        upk2(acc[i][1], out[2], out[3]);
        if (bias) {
#pragma unroll
            for (int j = 0; j < 4; j++) out[j] += bias[colb + j];
        }
        if (RELU) {
#pragma unroll
            for (int j = 0; j < 4; j++) out[j] = fmaxf(out[j], 0.f);
        }
        if (rowscale) {
            float rs = rowscale[row];
#pragma unroll
            for (int j = 0; j < 4; j++) out[j] *= rs;
        }
        if (addend) {
            const float* adp = addend + (long long)bz * sAdd + (long long)row * ldadd + colb;
#pragma unroll
            for (int j = 0; j < 4; j++) out[j] += adp[j];
        }
        *(float4*)(C + (long long)row * ldc + colb) =
            make_float4(out[0], out[1], out[2], out[3]);
    }
}

/* ------------- batched transpose: out[b][c][r] = in[b][r][c] ------------ */
__global__ void transpose_kernel(const float* __restrict__ in, float* __restrict__ out,
                                 int R, int C)
{
    __shared__ float tile[32][33];
    const long long boff = (long long)blockIdx.z * R * C;
    int x  = blockIdx.x * 32 + threadIdx.x;
    int y0 = blockIdx.y * 32 + threadIdx.y;
#pragma unroll
    for (int j = 0; j < 32; j += 8)
        tile[threadIdx.y + j][threadIdx.x] = in[boff + (long long)(y0 + j) * C + x];
    __syncthreads();
    int xo = blockIdx.y * 32 + threadIdx.x;
    int yo = blockIdx.x * 32 + threadIdx.y;
#pragma unroll
    for (int j = 0; j < 32; j += 8)
        out[boff + (long long)(yo + j) * R + xo] = tile[threadIdx.x][threadIdx.y + j];
}

/* ------------- inverse column-L1 norms of A: inv[b*256+m] = 1/max(sum_n|A|,1e-12) */
__global__ void colnorm_kernel(const float* __restrict__ A, float* __restrict__ inv)
{
    int g = blockIdx.x * blockDim.x + threadIdx.x;   /* 0..8191 */
    int b = g >> 8, m = g & 255;
    const float* base = A + (long long)b * 65536 + m;
    float s = 0.f;
#pragma unroll 8
    for (int n = 0; n < 256; n++) s += fabsf(base[n * 256]);
    inv[g] = 1.f / fmaxf(s, 1e-12f);
}

/* ------------- copy (8192 x 2048) into left half of (8192 x 4096) ------- */
__global__ void copycat_kernel(const float* __restrict__ src, float* __restrict__ dst)
{
    long long i = (long long)blockIdx.x * blockDim.x + threadIdx.x;  /* float4 idx */
    long long row = i >> 9;          /* / 512 */
    long long c4  = i & 511;
    ((float4*)dst)[(row << 10) + c4] = ((const float4*)src)[i];
}

/* ------------- masked Sinkhorn, one CTA per batch, data in global/L2 ---- */
__global__ __launch_bounds__(1024) void sinkhorn_kernel(
    float* __restrict__ buf, float* __restrict__ out,
    const int* __restrict__ n1, const int* __restrict__ iters_ptr)
{
    __shared__ float red[4 * 256];
    __shared__ float lsebuf[256];
    const int b = blockIdx.x;
    float* Mb = buf + (long long)b * 65536;
    const int nv = n1[b];
    const int iters = *iters_ptr;
    const int tid = threadIdx.x;
    const int warp = tid >> 5, lane = tid & 31;

    for (int idx = tid; idx < 65536; idx += 1024) {
        int r = idx >> 8;
        float v = Mb[idx];
        Mb[idx] = (r < nv) ? v / 0.05f : NEGV;
    }
    __syncthreads();

    for (int it = 0; it < iters; ++it) {
        if ((it & 1) == 0) {
            for (int r = warp; r < 256; r += 32) {
                float* rp = Mb + (r << 8);
                float v[8];
#pragma unroll
                for (int j = 0; j < 8; j++) v[j] = rp[lane + (j << 5)];
                float mx = v[0];
#pragma unroll
                for (int j = 1; j < 8; j++) mx = fmaxf(mx, v[j]);
#pragma unroll
                for (int o = 16; o > 0; o >>= 1)
                    mx = fmaxf(mx, __shfl_xor_sync(0xffffffffu, mx, o));
                float sm = 0.f;
#pragma unroll
                for (int j = 0; j < 8; j++) sm += expf(v[j] - mx);
#pragma unroll
                for (int o = 16; o > 0; o >>= 1)
                    sm += __shfl_xor_sync(0xffffffffu, sm, o);
                float lse = mx + logf(sm);
                bool ok = r < nv;
#pragma unroll
                for (int j = 0; j < 8; j++)
                    rp[lane + (j << 5)] = ok ? (v[j] - lse) : NEGV;
            }
            __syncthreads();
        } else {
            const int c = tid & 255, g = tid >> 8;
            float pm = NEGV;
            for (int r = g; r < 256; r += 4) pm = fmaxf(pm, Mb[(r << 8) + c]);
            red[(g << 8) + c] = pm;
            __syncthreads();
            if (tid < 256) {
                float cm = fmaxf(fmaxf(red[tid], red[256 + tid]),
                                 fmaxf(red[512 + tid], red[768 + tid]));
                lsebuf[tid] = cm;
            }
            __syncthreads();
            float cm = lsebuf[c];
            float ps = 0.f;
            for (int r = g; r < 256; r += 4) ps += expf(Mb[(r << 8) + c] - cm);
            red[(g << 8) + c] = ps;
            __syncthreads();
            if (tid < 256) {
                float s4 = red[tid] + red[256 + tid] + red[512 + tid] + red[768 + tid];
                lsebuf[tid] = lsebuf[tid] + logf(s4);
            }
            __syncthreads();
            for (int idx = tid; idx < 65536; idx += 1024) {
                int r = idx >> 8, cc = idx & 255;
                Mb[idx] = (r < nv) ? (Mb[idx] - lsebuf[cc]) : NEGV;
            }
            __syncthreads();
        }
    }
    float* ob = out + (long long)b * 65536;
    for (int idx = tid; idx < 65536; idx += 1024)
        ob[idx] = expf(Mb[idx]);
}

/* ------------- orchestration -------------------------------------------- */
extern "C" void kernel_launch(void* const* d_in, const int* in_sizes, int n_in,
                              void* d_out, int out_size)
{
    (void)in_sizes; (void)n_in; (void)out_size;
    const float* feat1 = (const float*)d_in[0];
    const float* feat2 = (const float*)d_in[1];
    const float* A1p   = (const float*)d_in[2];
    const float* A2p   = (const float*)d_in[3];
    const int*   n1p   = (const int*)d_in[4];
    const int*   skp   = (const int*)d_in[7];
    const float* W0a = (const float*)d_in[8],  *b0a = (const float*)d_in[9];
    const float* W0u = (const float*)d_in[10], *b0u = (const float*)d_in[11];
    const float* W1a = (const float*)d_in[12], *b1a = (const float*)d_in[13];
    const float* W1u = (const float*)d_in[14], *b1u = (const float*)d_in[15];
    const float* Wc  = (const float*)d_in[16], *bc  = (const float*)d_in[17];
    const float* Aaff0 = (const float*)d_in[18];
    const float* Aaff1 = (const float*)d_in[19];
    float* outp = (float*)d_out;

    float *ax, *ux, *e1, *e2, *tb, *m1, *m2, *e2t, *cat, *sb, *sbt, *col;
    cudaGetSymbolAddress((void**)&ax,  g_ax);
    cudaGetSymbolAddress((void**)&ux,  g_ux);
    cudaGetSymbolAddress((void**)&e1,  g_e1);
    cudaGetSymbolAddress((void**)&e2,  g_e2);
    cudaGetSymbolAddress((void**)&tb,  g_tb);
    cudaGetSymbolAddress((void**)&m1,  g_m1);
    cudaGetSymbolAddress((void**)&m2,  g_m2);
    cudaGetSymbolAddress((void**)&e2t, g_e2t);
    cudaGetSymbolAddress((void**)&cat, g_cat);
    cudaGetSymbolAddress((void**)&sb,  g_sb);
    cudaGetSymbolAddress((void**)&sbt, g_sbt);
    cudaGetSymbolAddress((void**)&col, g_col);

    cudaFuncSetAttribute(gemm_k<true >, cudaFuncAttributeMaxDynamicSharedMemorySize, SMEMB);
    cudaFuncSetAttribute(gemm_k<false>, cudaFuncAttributeMaxDynamicSharedMemorySize, SMEMB);

    const dim3 blk(512);
    const dim3 tblk(32, 8);
    const long long SE = 256LL * 2048;
    const long long SS = 65536LL;
    const long long SCAT = 256LL * 4096;

    colnorm_kernel<<<32, 256>>>(A1p, col);
    colnorm_kernel<<<32, 256>>>(A2p, col + ROWS);

    /* ---- gconv layer 0 ---- */
    gemm_k<true ><<<dim3(64,16,1), blk, SMEMB>>>(8192,2048,1024, feat1,1024,0, W0a,2048,0, ax,2048,0, b0a, col,      nullptr,0,0);
    gemm_k<true ><<<dim3(64,16,1), blk, SMEMB>>>(8192,2048,1024, feat1,1024,0, W0u,2048,0, ux,2048,0, b0u, nullptr,  nullptr,0,0);
    gemm_k<false><<<dim3(2,16,32), blk, SMEMB>>>(256,2048,256, A1p,256,SS, ax,2048,SE, e1,2048,SE, nullptr,nullptr, ux,2048,SE);
    gemm_k<true ><<<dim3(64,16,1), blk, SMEMB>>>(8192,2048,1024, feat2,1024,0, W0a,2048,0, ax,2048,0, b0a, col+ROWS, nullptr,0,0);
    gemm_k<true ><<<dim3(64,16,1), blk, SMEMB>>>(8192,2048,1024, feat2,1024,0, W0u,2048,0, ux,2048,0, b0u, nullptr,  nullptr,0,0);
    gemm_k<false><<<dim3(2,16,32), blk, SMEMB>>>(256,2048,256, A2p,256,SS, ax,2048,SE, e2,2048,SE, nullptr,nullptr, ux,2048,SE);

    /* ---- affinity 0: s = (e1 @ Aaff0) @ e2^T  (via e2 transpose) ---- */
    gemm_k<false><<<dim3(64,16,1), blk, SMEMB>>>(8192,2048,2048, e1,2048,0, Aaff0,2048,0, tb,2048,0, nullptr,nullptr,nullptr,0,0);
    transpose_kernel<<<dim3(64,8,32), tblk>>>(e2, e2t, 256, 2048);
    gemm_k<false><<<dim3(2,2,32),  blk, SMEMB>>>(256,256,2048, tb,2048,SE, e2t,256,SE, sb,256,SS, nullptr,nullptr,nullptr,0,0);
    sinkhorn_kernel<<<32, 1024>>>(sb, sb, n1p, skp);

    /* ---- cross update ---- */
    copycat_kernel<<<16384, 256>>>(e1, cat);
    gemm_k<false><<<dim3(2,16,32), blk, SMEMB>>>(256,2048,256, sb,256,SS, e2,2048,SE, cat+2048,4096,SCAT, nullptr,nullptr,nullptr,0,0);
    gemm_k<false><<<dim3(64,16,1), blk, SMEMB>>>(8192,2048,4096, cat,4096,0, Wc,2048,0, m1,2048,0, bc, nullptr, nullptr,0,0);
    copycat_kernel<<<16384, 256>>>(e2, cat);
    transpose_kernel<<<dim3(8,8,32), tblk>>>(sb, sbt, 256, 256);
    gemm_k<false><<<dim3(2,16,32), blk, SMEMB>>>(256,2048,256, sbt,256,SS, e1,2048,SE, cat+2048,4096,SCAT, nullptr,nullptr,nullptr,0,0);
    gemm_k<false><<<dim3(64,16,1), blk, SMEMB>>>(8192,2048,4096, cat,4096,0, Wc,2048,0, m2,2048,0, bc, nullptr, nullptr,0,0);

    /* ---- gconv layer 1 ---- */
    gemm_k<true ><<<dim3(64,16,1), blk, SMEMB>>>(8192,2048,2048, m1,2048,0, W1a,2048,0, ax,2048,0, b1a, col,      nullptr,0,0);
    gemm_k<true ><<<dim3(64,16,1), blk, SMEMB>>>(8192,2048,2048, m1,2048,0, W1u,2048,0, ux,2048,0, b1u, nullptr,  nullptr,0,0);
    gemm_k<false><<<dim3(2,16,32), blk, SMEMB>>>(256,2048,256, A1p,256,SS, ax,2048,SE, e1,2048,SE, nullptr,nullptr, ux,2048,SE);
    gemm_k<true ><<<dim3(64,16,1), blk, SMEMB>>>(8192,2048,2048, m2,2048,0, W1a,2048,0, ax,2048,0, b1a, col+ROWS, nullptr,0,0);
    gemm_k<true ><<<dim3(64,16,1), blk, SMEMB>>>(8192,2048,2048, m2,2048,0, W1u,2048,0, ux,2048,0, b1u, nullptr,  nullptr,0,0);
    gemm_k<false><<<dim3(2,16,32), blk, SMEMB>>>(256,2048,256, A2p,256,SS, ax,2048,SE, e2,2048,SE, nullptr,nullptr, ux,2048,SE);

    /* ---- affinity 1 + final sinkhorn -> output ---- */
    gemm_k<false><<<dim3(64,16,1), blk, SMEMB>>>(8192,2048,2048, e1,2048,0, Aaff1,2048,0, tb,2048,0, nullptr,nullptr,nullptr,0,0);
    transpose_kernel<<<dim3(64,8,32), tblk>>>(e2, e2t, 256, 2048);
    gemm_k<false><<<dim3(2,2,32),  blk, SMEMB>>>(256,256,2048, tb,2048,SE, e2t,256,SE, sb,256,SS, nullptr,nullptr,nullptr,0,0);
    sinkhorn_kernel<<<32, 1024>>>(sb, outp, n1p, skp);
}